// round 3
// baseline (speedup 1.0000x reference)
#include <cuda_runtime.h>
#include <math.h>

#define NB 16
#define NL 128
#define NH 256
#define ND 300
#define NE 34
#define NA 36

__device__ float d_zx[2][NL][NB][4*NH];
__device__ float d_hidden[NB][NL][2*NH];
__device__ float d_hcur[2][2][NB][NH];
__device__ float d_S [NB][NL][NA];
__device__ float d_T [NB][NL][NA];
__device__ float d_E0[NB][NL][NE];
__device__ unsigned g_cnt = 0;
__device__ unsigned g_gen = 0;

__device__ __forceinline__ float sigf(float x){ return 1.f/(1.f + expf(-x)); }

// K1: zx = gather(emb, ids) @ Wih^T + (bih+bhh), both directions fused.
__global__ void __launch_bounds__(256) k1_zx(const int* __restrict__ ids,
        const float* __restrict__ emb,
        const float* __restrict__ WihF, const float* __restrict__ WihB,
        const float* __restrict__ bihF, const float* __restrict__ bhhF,
        const float* __restrict__ bihB, const float* __restrict__ bhhB)
{
    __shared__ __align__(16) float As[16][68];
    __shared__ __align__(16) float Bs[16][68];
    __shared__ int ids_s[64];
    const int tid = threadIdx.x;
    const int m0 = blockIdx.y * 64;
    const int n0 = blockIdx.x * 64;
    if (tid < 64) ids_s[tid] = ids[m0 + tid];
    __syncthreads();
    const int lm = tid & 63;
    const int k4 = tid >> 6;
    const int ty = tid >> 4;
    const int tx = tid & 15;
    float acc[4][4];
    #pragma unroll
    for (int i=0;i<4;i++){ acc[i][0]=0.f; acc[i][1]=0.f; acc[i][2]=0.f; acc[i][3]=0.f; }

    for (int kt = 0; kt < 19; kt++) {
        const int k0 = kt*16 + k4*4;
        {
            const int id = ids_s[lm];
            const float* src = emb + (long)id*ND + k0;
            float v0=0.f,v1=0.f,v2=0.f,v3=0.f;
            if (k0 + 3 < ND) { float4 t4 = *(const float4*)src; v0=t4.x;v1=t4.y;v2=t4.z;v3=t4.w; }
            else {
                if (k0+0 < ND) v0 = src[0];
                if (k0+1 < ND) v1 = src[1];
                if (k0+2 < ND) v2 = src[2];
            }
            As[k4*4+0][lm]=v0; As[k4*4+1][lm]=v1; As[k4*4+2][lm]=v2; As[k4*4+3][lm]=v3;
        }
        {
            const int n = n0 + lm;
            const float* wr = (n < 1024) ? (WihF + (long)n*ND) : (WihB + (long)(n-1024)*ND);
            const float* src = wr + k0;
            float v0=0.f,v1=0.f,v2=0.f,v3=0.f;
            if (k0 + 3 < ND) { float4 t4 = *(const float4*)src; v0=t4.x;v1=t4.y;v2=t4.z;v3=t4.w; }
            else {
                if (k0+0 < ND) v0 = src[0];
                if (k0+1 < ND) v1 = src[1];
                if (k0+2 < ND) v2 = src[2];
            }
            Bs[k4*4+0][lm]=v0; Bs[k4*4+1][lm]=v1; Bs[k4*4+2][lm]=v2; Bs[k4*4+3][lm]=v3;
        }
        __syncthreads();
        #pragma unroll
        for (int kk = 0; kk < 16; kk++) {
            const float4 a4 = *(const float4*)&As[kk][ty*4];
            const float4 b4 = *(const float4*)&Bs[kk][tx*4];
            const float av[4] = {a4.x,a4.y,a4.z,a4.w};
            const float bv[4] = {b4.x,b4.y,b4.z,b4.w};
            #pragma unroll
            for (int i=0;i<4;i++){
                #pragma unroll
                for (int jj=0;jj<4;jj++) acc[i][jj] = fmaf(av[i], bv[jj], acc[i][jj]);
            }
        }
        __syncthreads();
    }
    #pragma unroll
    for (int jj=0;jj<4;jj++){
        const int n = n0 + tx*4 + jj;
        const float bias = (n < 1024) ? (bihF[n] + bhhF[n]) : (bihB[n-1024] + bhhB[n-1024]);
        #pragma unroll
        for (int i=0;i<4;i++){
            const int m = m0 + ty*4 + i;
            const int bb = m >> 7, t = m & 127;
            const float v = acc[i][jj] + bias;
            if (n < 1024) d_zx[0][t][bb][n]      = v;
            else          d_zx[1][t][bb][n-1024] = v;
        }
    }
}

// K2: persistent BiLSTM, grid barrier per step.
__global__ void __launch_bounds__(256) k2_lstm(const float* __restrict__ WhhF,
                                               const float* __restrict__ WhhB)
{
    __shared__ __align__(16) float W_s[16][260];
    __shared__ __align__(16) float h_s[16][260];
    __shared__ float zp[16][16][4];
    __shared__ float zs[16][16];
    const int tid = threadIdx.x;
    const int bx  = blockIdx.x;
    const int dir = bx >> 6;
    const int sub = bx & 63;
    const int u0  = sub * 4;
    const float* Whh = dir ? WhhB : WhhF;

    for (int idx = tid; idx < 16*256; idx += 256){
        const int rl = idx >> 8, k = idx & 255;
        const int rg = (rl >> 2) * 256 + u0 + (rl & 3);
        W_s[rl][k] = Whh[(long)rg*256 + k];
    }

    const int lane = tid & 31, w = tid >> 5;
    const int bdot = lane & 15;
    const int rq   = (lane >> 4) + 2*(w & 1);
    const int kq   = w >> 1;

    float creg = 0.f;
    const int cb = tid & 15, cu = (tid >> 4) & 3;

    unsigned mygen = *(volatile unsigned*)&g_gen;
    __syncthreads();

    for (int t = 0; t < NL; t++){
        const int xt = dir ? (NL-1-t) : t;
        const int wb = t & 1, rb = 1 - wb;
        if (t == 0){
            for (int idx = tid; idx < NB*NH; idx += 256)
                h_s[idx >> 8][idx & 255] = 0.f;
        } else {
            const float* hp = &d_hcur[dir][rb][0][0];
            for (int idx = tid; idx < NB*NH; idx += 256)
                h_s[idx >> 8][idx & 255] = __ldcg(hp + idx);
        }
        __syncthreads();
        float4 hreg[16];
        #pragma unroll
        for (int i=0;i<16;i++) hreg[i] = *(const float4*)&h_s[bdot][kq*64 + i*4];
        float acc[4] = {0.f,0.f,0.f,0.f};
        #pragma unroll
        for (int i=0;i<16;i++){
            const float4 hv = hreg[i];
            #pragma unroll
            for (int rr=0;rr<4;rr++){
                const float4 wv = *(const float4*)&W_s[rq*4+rr][kq*64 + i*4];
                float a = acc[rr];
                a = fmaf(hv.x, wv.x, a);
                a = fmaf(hv.y, wv.y, a);
                a = fmaf(hv.z, wv.z, a);
                a = fmaf(hv.w, wv.w, a);
                acc[rr] = a;
            }
        }
        #pragma unroll
        for (int rr=0;rr<4;rr++) zp[rq*4+rr][bdot][kq] = acc[rr];
        __syncthreads();
        {
            const int row = tid & 15, bb = tid >> 4;
            const int rg = (row >> 2)*256 + u0 + (row & 3);
            zs[row][bb] = d_zx[dir][xt][bb][rg]
                        + ((zp[row][bb][0] + zp[row][bb][1]) + (zp[row][bb][2] + zp[row][bb][3]));
        }
        __syncthreads();
        if (tid < 64){
            const float zi = zs[cu     ][cb];
            const float zf = zs[4  + cu][cb];
            const float zg = zs[8  + cu][cb];
            const float zo = zs[12 + cu][cb];
            creg = sigf(zf)*creg + sigf(zi)*tanhf(zg);
            const float h = sigf(zo)*tanhf(creg);
            const int u = u0 + cu;
            __stcg(&d_hcur[dir][wb][cb][u], h);
            d_hidden[cb][xt][dir*NH + u] = h;
        }
        mygen++;
        __syncthreads();
        if (tid == 0){
            __threadfence();
            const unsigned prev = atomicAdd(&g_cnt, 1u);
            if (prev == 127u){
                g_cnt = 0u;
                __threadfence();
                atomicExch(&g_gen, mygen);
            } else {
                while ((int)(*(volatile unsigned*)&g_gen - mygen) < 0) __nanosleep(64);
            }
            __threadfence();
        }
        __syncthreads();
    }
}

// K3: per-token static decode projections S, T, E0.
__global__ void __launch_bounds__(128) k3_pre(const float* __restrict__ Wa,
        const float* __restrict__ We,
        const float* __restrict__ ba, const float* __restrict__ be)
{
    __shared__ __align__(16) float hid_s[8][516];
    const int tid = threadIdx.x;
    const int m0 = blockIdx.x * 8;
    const float* hbase = &d_hidden[0][0][0] + (long)m0 * 512;
    for (int idx = tid; idx < 8*512; idx += 128)
        hid_s[idx >> 9][idx & 511] = hbase[idx];
    __syncthreads();
    const int tok = tid >> 4, slot = tid & 15;
    const int m = m0 + tok;
    const float* hv = hid_s[tok];
    for (int cc = slot; cc < 106; cc += 16){
        float acc = 0.f;
        if (cc < 72){
            const float* wr = Wa + (long)(cc < 36 ? cc : cc-36) * 1092 + (cc < 36 ? 0 : 512);
            #pragma unroll 4
            for (int k = 0; k < 512; k += 4){
                const float4 w4 = *(const float4*)(wr + k);
                const float4 h4 = *(const float4*)(hv + k);
                acc = fmaf(h4.x, w4.x, acc);
                acc = fmaf(h4.y, w4.y, acc);
                acc = fmaf(h4.z, w4.z, acc);
                acc = fmaf(h4.w, w4.w, acc);
            }
            if (cc < 36) { acc += ba[cc]; (&d_S[0][0][0])[(long)m*36 + cc]      = acc; }
            else         {               (&d_T[0][0][0])[(long)m*36 + (cc-36)] = acc; }
        } else {
            const int e = cc - 72;
            const float* wr = We + (long)e * 545;
            #pragma unroll 4
            for (int k = 0; k < 512; k += 4){
                acc = fmaf(hv[k+0], wr[k+0], acc);
                acc = fmaf(hv[k+1], wr[k+1], acc);
                acc = fmaf(hv[k+2], wr[k+2], acc);
                acc = fmaf(hv[k+3], wr[k+3], acc);
            }
            acc += be[e];
            (&d_E0[0][0][0])[(long)m*34 + e] = acc;
        }
    }
}

// K4: decode scan, one block per batch, one thread per position j.
__global__ void __launch_bounds__(128) k4_scan(const float* __restrict__ Wa,
        const float* __restrict__ We,
        float* __restrict__ evout, float* __restrict__ argout)
{
    __shared__ float Wag1_s[35][36];
    __shared__ float Wag2_s[33][36];
    __shared__ float Weg_s [33][34];
    __shared__ float T_s[36];
    __shared__ float evl_s[34];
    __shared__ float Gt_s[34];
    __shared__ int ev_pred_s;
    __shared__ int newev_s;

    const int tid = threadIdx.x;
    const int b = blockIdx.x;
    for (int idx = tid; idx < 35*36; idx += 128){
        const int k = idx / 36, a = idx % 36;
        Wag1_s[k][a] = Wa[(long)a*1092 + 1024 + k];
    }
    for (int idx = tid; idx < 33*36; idx += 128){
        const int k = idx / 36, a = idx % 36;
        Wag2_s[k][a] = Wa[(long)a*1092 + 1059 + k];
    }
    for (int idx = tid; idx < 33*34; idx += 128){
        const int k = idx / 34, e = idx % 34;
        Weg_s[k][e] = We[(long)e*545 + 512 + k];
    }
    if (tid < 34) Gt_s[tid] = 0.f;

    const int j = tid;
    float Sreg[36], G[36];
    #pragma unroll
    for (int a=0;a<36;a++){ Sreg[a] = d_S[b][j][a]; G[a] = 0.f; }
    unsigned long long garg = 0ull, gta = 0ull, gtrg = 0ull;
    __syncthreads();

    for (int i = 0; i < NL; i++){
        if (tid < 36) T_s[tid] = d_T[b][i][tid];
        if (tid >= 64 && tid < 98){
            const int e = tid - 64;
            const float v = d_E0[b][i][e] + Gt_s[e];
            evl_s[e] = v;
            evout[((long)b*NL + i)*NE + e] = v;
        }
        __syncthreads();

        float* op = argout + (((long)b*NL + i)*NL + j)*NA;
        int am = 0; float bm = -1e30f;
        #pragma unroll
        for (int a4 = 0; a4 < 9; a4++){
            const float v0 = Sreg[a4*4+0] + T_s[a4*4+0] + G[a4*4+0];
            const float v1 = Sreg[a4*4+1] + T_s[a4*4+1] + G[a4*4+1];
            const float v2 = Sreg[a4*4+2] + T_s[a4*4+2] + G[a4*4+2];
            const float v3 = Sreg[a4*4+3] + T_s[a4*4+3] + G[a4*4+3];
            if (v0 > bm){ bm = v0; am = a4*4+0; }
            if (v1 > bm){ bm = v1; am = a4*4+1; }
            if (v2 > bm){ bm = v2; am = a4*4+2; }
            if (v3 > bm){ bm = v3; am = a4*4+3; }
            float4 v4; v4.x=v0; v4.y=v1; v4.z=v2; v4.w=v3;
            *(float4*)(op + a4*4) = v4;
        }

        if (tid == 0){
            float bme = evl_s[0]; int ame = 0;
            #pragma unroll
            for (int e=1;e<34;e++){
                const float v = evl_s[e];
                if (v > bme){ bme = v; ame = e; }
            }
            int ne = 0;
            if (ame > 0 && !((gtrg >> (ame-1)) & 1ull)){ gtrg |= 1ull << (ame-1); ne = 1; }
            ev_pred_s = ame;
            newev_s = ne;
        }
        __syncthreads();

        const int ep = ev_pred_s;
        if (newev_s && tid < 34) Gt_s[tid] += Weg_s[ep-1][tid];
        if (ep > 0 && am > 0){
            const int ke = ep - 1;
            if (!((gta >> ke) & 1ull)){
                gta |= 1ull << ke;
                #pragma unroll
                for (int a=0;a<36;a++) G[a] += Wag2_s[ke][a];
            }
            const int ak = am - 1;
            if (!((garg >> ak) & 1ull)){
                garg |= 1ull << ak;
                #pragma unroll
                for (int a=0;a<36;a++) G[a] += Wag1_s[ak][a];
            }
        }
        __syncthreads();
    }
}

extern "C" void kernel_launch(void* const* d_in, const int* in_sizes, int n_in,
                              void* d_out, int out_size)
{
    const int*   ids  = (const int*)  d_in[0];
    const float* emb  = (const float*)d_in[1];
    const float* WihF = (const float*)d_in[2];
    const float* WhhF = (const float*)d_in[3];
    const float* bihF = (const float*)d_in[4];
    const float* bhhF = (const float*)d_in[5];
    const float* WihB = (const float*)d_in[6];
    const float* WhhB = (const float*)d_in[7];
    const float* bihB = (const float*)d_in[8];
    const float* bhhB = (const float*)d_in[9];
    const float* We   = (const float*)d_in[10];
    const float* be   = (const float*)d_in[11];
    const float* Wa   = (const float*)d_in[12];
    const float* ba   = (const float*)d_in[13];
    float* out    = (float*)d_out;
    float* evout  = out;
    float* argout = out + (long)NB*NL*NE;

    k1_zx<<<dim3(32, 32), 256>>>(ids, emb, WihF, WihB, bihF, bhhF, bihB, bhhB);
    k2_lstm<<<128, 256>>>(WhhF, WhhB);
    k3_pre<<<256, 128>>>(Wa, We, ba, be);
    k4_scan<<<16, 128>>>(Wa, We, evout, argout);
}

// round 4
// speedup vs baseline: 1.0792x; 1.0792x over previous
#include <cuda_runtime.h>
#include <math.h>

#define NB 16
#define NL 128
#define NH 256
#define ND 300
#define NE 34
#define NA 36

__device__ float d_zx[2][NL][NB][4*NH];
__device__ float d_hidden[NB][NL][2*NH];
__device__ float d_hcur[2][2][NB][NH];
__device__ float d_S [NB][NL][NA];
__device__ float d_T [NB][NL][NA];
__device__ float d_E0[NB][NL][NE];
__device__ unsigned g_grp[16*32];   // 16 groups, 128B apart
__device__ unsigned g_root = 0;
__device__ unsigned g_gen  = 0;

__device__ __forceinline__ float sigf(float x){ return 1.f/(1.f + expf(-x)); }

// ============================================================================
// K1: zx = gather(emb, ids) @ Wih^T + (bih+bhh), both directions fused.
// ============================================================================
__global__ void __launch_bounds__(256) k1_zx(const int* __restrict__ ids,
        const float* __restrict__ emb,
        const float* __restrict__ WihF, const float* __restrict__ WihB,
        const float* __restrict__ bihF, const float* __restrict__ bhhF,
        const float* __restrict__ bihB, const float* __restrict__ bhhB)
{
    __shared__ __align__(16) float As[16][68];
    __shared__ __align__(16) float Bs[16][68];
    __shared__ int ids_s[64];
    const int tid = threadIdx.x;
    const int m0 = blockIdx.y * 64;
    const int n0 = blockIdx.x * 64;
    if (tid < 64) ids_s[tid] = ids[m0 + tid];
    __syncthreads();
    const int lm = tid & 63;
    const int k4 = tid >> 6;
    const int ty = tid >> 4;
    const int tx = tid & 15;
    float acc[4][4];
    #pragma unroll
    for (int i=0;i<4;i++){ acc[i][0]=0.f; acc[i][1]=0.f; acc[i][2]=0.f; acc[i][3]=0.f; }

    for (int kt = 0; kt < 19; kt++) {
        const int k0 = kt*16 + k4*4;
        {
            const int id = ids_s[lm];
            const float* src = emb + (long)id*ND + k0;
            float v0=0.f,v1=0.f,v2=0.f,v3=0.f;
            if (k0 + 3 < ND) { float4 t4 = *(const float4*)src; v0=t4.x;v1=t4.y;v2=t4.z;v3=t4.w; }
            else {
                if (k0+0 < ND) v0 = src[0];
                if (k0+1 < ND) v1 = src[1];
                if (k0+2 < ND) v2 = src[2];
            }
            As[k4*4+0][lm]=v0; As[k4*4+1][lm]=v1; As[k4*4+2][lm]=v2; As[k4*4+3][lm]=v3;
        }
        {
            const int n = n0 + lm;
            const float* wr = (n < 1024) ? (WihF + (long)n*ND) : (WihB + (long)(n-1024)*ND);
            const float* src = wr + k0;
            float v0=0.f,v1=0.f,v2=0.f,v3=0.f;
            if (k0 + 3 < ND) { float4 t4 = *(const float4*)src; v0=t4.x;v1=t4.y;v2=t4.z;v3=t4.w; }
            else {
                if (k0+0 < ND) v0 = src[0];
                if (k0+1 < ND) v1 = src[1];
                if (k0+2 < ND) v2 = src[2];
            }
            Bs[k4*4+0][lm]=v0; Bs[k4*4+1][lm]=v1; Bs[k4*4+2][lm]=v2; Bs[k4*4+3][lm]=v3;
        }
        __syncthreads();
        #pragma unroll
        for (int kk = 0; kk < 16; kk++) {
            const float4 a4 = *(const float4*)&As[kk][ty*4];
            const float4 b4 = *(const float4*)&Bs[kk][tx*4];
            const float av[4] = {a4.x,a4.y,a4.z,a4.w};
            const float bv[4] = {b4.x,b4.y,b4.z,b4.w};
            #pragma unroll
            for (int i=0;i<4;i++){
                #pragma unroll
                for (int jj=0;jj<4;jj++) acc[i][jj] = fmaf(av[i], bv[jj], acc[i][jj]);
            }
        }
        __syncthreads();
    }
    #pragma unroll
    for (int jj=0;jj<4;jj++){
        const int n = n0 + tx*4 + jj;
        const float bias = (n < 1024) ? (bihF[n] + bhhF[n]) : (bihB[n-1024] + bhhB[n-1024]);
        #pragma unroll
        for (int i=0;i<4;i++){
            const int m = m0 + ty*4 + i;
            const int bb = m >> 7, t = m & 127;
            const float v = acc[i][jj] + bias;
            if (n < 1024) d_zx[0][t][bb][n]      = v;
            else          d_zx[1][t][bb][n-1024] = v;
        }
    }
}

// ============================================================================
// K2: persistent BiLSTM. 128 blocks x 512 threads; 2-level tree grid barrier
// with generation counters (no resets; bases derived from g_gen at start).
// ============================================================================
__global__ void __launch_bounds__(512) k2_lstm(const float* __restrict__ WhhF,
                                               const float* __restrict__ WhhB)
{
    __shared__ __align__(16) float W_s[16][260];
    __shared__ __align__(16) float h_s[16][260];
    __shared__ float zp[16][16][8];
    const int tid = threadIdx.x;
    const int bx  = blockIdx.x;
    const int dir = bx >> 6;
    const int sub = bx & 63;
    const int u0  = sub * 4;
    const float* Whh = dir ? WhhB : WhhF;

    for (int idx = tid; idx < 16*256; idx += 512){
        const int rl = idx >> 8, k = idx & 255;
        const int rg = (rl >> 2) * 256 + u0 + (rl & 3);
        W_s[rl][k] = Whh[(long)rg*256 + k];
    }

    const int lane = tid & 31, w = tid >> 5;   // 16 warps
    const int bdot = lane & 15;
    const int rq   = (lane >> 4) + 2*(w & 1);  // 0..3
    const int kq   = w >> 1;                   // 0..7 (32-wide k slice)

    float creg = 0.f;
    const int cb = tid & 15, cu = (tid >> 4) & 3;   // for tid<64

    const unsigned G0 = *(volatile unsigned*)&g_gen;   // static at launch start
    const int grp = bx >> 3;                           // 16 groups of 8
    __syncthreads();

    for (unsigned t = 0; t < NL; t++){
        const int xt = dir ? (NL-1-(int)t) : (int)t;
        const int wb = t & 1, rb = 1 - wb;

        // prefetch this step's zx for the gate phase (independent of h)
        float zx4[4];
        if (tid < 64){
            const float* zb = &d_zx[dir][xt][cb][0];
            #pragma unroll
            for (int g=0; g<4; g++) zx4[g] = __ldg(zb + g*256 + u0 + cu);
        }

        // stage previous h into smem
        if (t == 0){
            for (int idx = tid; idx < 16*256; idx += 512)
                h_s[idx >> 8][idx & 255] = 0.f;
        } else {
            const float4* hp = (const float4*)&d_hcur[dir][rb][0][0];
            for (int idx = tid; idx < 1024; idx += 512){
                float4 v = __ldcg(hp + idx);
                *(float4*)&h_s[idx >> 6][(idx*4) & 255] = v;
            }
        }
        __syncthreads();

        // dot: 4 rows x 1 batch x 32 k per thread
        float4 hreg[8];
        #pragma unroll
        for (int i=0;i<8;i++) hreg[i] = *(const float4*)&h_s[bdot][kq*32 + i*4];
        float acc[4] = {0.f,0.f,0.f,0.f};
        #pragma unroll
        for (int i=0;i<8;i++){
            const float4 hv = hreg[i];
            #pragma unroll
            for (int rr=0;rr<4;rr++){
                const float4 wv = *(const float4*)&W_s[rq*4+rr][kq*32 + i*4];
                float a = acc[rr];
                a = fmaf(hv.x, wv.x, a);
                a = fmaf(hv.y, wv.y, a);
                a = fmaf(hv.z, wv.z, a);
                a = fmaf(hv.w, wv.w, a);
                acc[rr] = a;
            }
        }
        #pragma unroll
        for (int rr=0;rr<4;rr++) zp[rq*4+rr][bdot][kq] = acc[rr];
        __syncthreads();

        // gates: combine partials + zx, nonlinearity, write h
        if (tid < 64){
            float z[4];
            #pragma unroll
            for (int g=0; g<4; g++){
                float s = zx4[g];
                #pragma unroll
                for (int q=0; q<8; q++) s += zp[g*4+cu][cb][q];
                z[g] = s;
            }
            creg = sigf(z[1])*creg + sigf(z[0])*tanhf(z[2]);
            const float h = sigf(z[3])*tanhf(creg);
            const int u = u0 + cu;
            __stcg(&d_hcur[dir][wb][cb][u], h);
            d_hidden[cb][xt][dir*NH + u] = h;
        }
        __syncthreads();

        // tree grid barrier (skip after last step)
        if (t < NL-1){
            if (tid == 0){
                __threadfence();
                const unsigned want = G0 + t + 1u;
                const unsigned p = atomicAdd(&g_grp[grp*32], 1u);
                if (p == G0*8u + t*8u + 7u){
                    const unsigned q = atomicAdd(&g_root, 1u);
                    if (q == G0*16u + t*16u + 15u){
                        atomicExch(&g_gen, want);
                    } else {
                        while ((int)(*(volatile unsigned*)&g_gen - want) < 0) {}
                    }
                } else {
                    while ((int)(*(volatile unsigned*)&g_gen - want) < 0) {}
                }
                __threadfence();
            }
            __syncthreads();
        }
    }
}

// ============================================================================
// K3: per-token static decode projections S, T, E0.
// ============================================================================
__global__ void __launch_bounds__(128) k3_pre(const float* __restrict__ Wa,
        const float* __restrict__ We,
        const float* __restrict__ ba, const float* __restrict__ be)
{
    __shared__ __align__(16) float hid_s[8][516];
    const int tid = threadIdx.x;
    const int m0 = blockIdx.x * 8;
    const float* hbase = &d_hidden[0][0][0] + (long)m0 * 512;
    for (int idx = tid; idx < 8*512; idx += 128)
        hid_s[idx >> 9][idx & 511] = hbase[idx];
    __syncthreads();
    const int tok = tid >> 4, slot = tid & 15;
    const int m = m0 + tok;
    const float* hv = hid_s[tok];
    for (int cc = slot; cc < 106; cc += 16){
        float acc = 0.f;
        if (cc < 72){
            const float* wr = Wa + (long)(cc < 36 ? cc : cc-36) * 1092 + (cc < 36 ? 0 : 512);
            #pragma unroll 4
            for (int k = 0; k < 512; k += 4){
                const float4 w4 = *(const float4*)(wr + k);
                const float4 h4 = *(const float4*)(hv + k);
                acc = fmaf(h4.x, w4.x, acc);
                acc = fmaf(h4.y, w4.y, acc);
                acc = fmaf(h4.z, w4.z, acc);
                acc = fmaf(h4.w, w4.w, acc);
            }
            if (cc < 36) { acc += ba[cc]; (&d_S[0][0][0])[(long)m*36 + cc]      = acc; }
            else         {               (&d_T[0][0][0])[(long)m*36 + (cc-36)] = acc; }
        } else {
            const int e = cc - 72;
            const float* wr = We + (long)e * 545;
            #pragma unroll 4
            for (int k = 0; k < 512; k += 4){
                acc = fmaf(hv[k+0], wr[k+0], acc);
                acc = fmaf(hv[k+1], wr[k+1], acc);
                acc = fmaf(hv[k+2], wr[k+2], acc);
                acc = fmaf(hv[k+3], wr[k+3], acc);
            }
            acc += be[e];
            (&d_E0[0][0][0])[(long)m*34 + e] = acc;
        }
    }
}

// ============================================================================
// K4: decode scan. 16 blocks (one per batch), 128 threads (one per position).
// T resident in smem; E0 prefetched one iter ahead; warp-shfl event argmax.
// ============================================================================
__global__ void __launch_bounds__(128) k4_scan(const float* __restrict__ Wa,
        const float* __restrict__ We,
        float* __restrict__ evout, float* __restrict__ argout)
{
    __shared__ float Ts[NL*NA];        // 18432 B
    __shared__ float Wag1_s[35][36];
    __shared__ float Wag2_s[33][36];
    __shared__ float Weg_s [33][34];
    __shared__ float Gt_s[34];
    __shared__ int ev_pred_s;
    __shared__ int newev_s;

    const int tid = threadIdx.x;
    const int b = blockIdx.x;
    for (int idx = tid; idx < NL*NA; idx += 128)
        Ts[idx] = (&d_T[b][0][0])[idx];
    for (int idx = tid; idx < 35*36; idx += 128){
        const int k = idx / 36, a = idx % 36;
        Wag1_s[k][a] = Wa[(long)a*1092 + 1024 + k];
    }
    for (int idx = tid; idx < 33*36; idx += 128){
        const int k = idx / 36, a = idx % 36;
        Wag2_s[k][a] = Wa[(long)a*1092 + 1059 + k];
    }
    for (int idx = tid; idx < 33*34; idx += 128){
        const int k = idx / 34, e = idx % 34;
        Weg_s[k][e] = We[(long)e*545 + 512 + k];
    }
    if (tid < 34) Gt_s[tid] = 0.f;

    const int j = tid;
    float Sreg[36], G[36];
    #pragma unroll
    for (int a=0;a<36;a++){ Sreg[a] = d_S[b][j][a]; G[a] = 0.f; }
    unsigned long long garg = 0ull, gta = 0ull, gtrg = 0ull;

    const float* E0b = &d_E0[b][0][0];
    float e0a = (tid < 32) ? __ldg(E0b + tid)      : 0.f;
    float e0b = (tid <  2) ? __ldg(E0b + 32 + tid) : 0.f;
    __syncthreads();

    for (int i = 0; i < NL; i++){
        // prefetch next E0 row
        float e0a_n = 0.f, e0b_n = 0.f;
        if (i < NL-1){
            if (tid < 32) e0a_n = __ldg(E0b + (i+1)*34 + tid);
            if (tid <  2) e0b_n = __ldg(E0b + (i+1)*34 + 32 + tid);
        }

        // event path: warp 0
        if (tid < 32){
            const float va = e0a + Gt_s[tid];
            const float vb = (tid < 2) ? (e0b + Gt_s[32+tid]) : -3.0e38f;
            evout[((long)b*NL + i)*NE + tid] = va;
            if (tid < 2) evout[((long)b*NL + i)*NE + 32 + tid] = vb;
            float bv = va; int bi = tid;
            if (vb > bv){ bv = vb; bi = 32 + tid; }
            #pragma unroll
            for (int off = 16; off; off >>= 1){
                const float ov = __shfl_xor_sync(0xffffffffu, bv, off);
                const int   oi = __shfl_xor_sync(0xffffffffu, bi, off);
                if (ov > bv || (ov == bv && oi < bi)){ bv = ov; bi = oi; }
            }
            if (tid == 0){
                const int ame = bi;
                int ne = 0;
                if (ame > 0 && !((gtrg >> (ame-1)) & 1ull)){ gtrg |= 1ull << (ame-1); ne = 1; }
                ev_pred_s = ame;
                newev_s = ne;
            }
        }

        // arg path: all threads (independent of this step's event)
        float* op = argout + (((long)b*NL + i)*NL + j)*NA;
        const float* Ti = &Ts[i*NA];
        int am = 0; float bm = -1e30f;
        #pragma unroll
        for (int a4 = 0; a4 < 9; a4++){
            const float v0 = Sreg[a4*4+0] + Ti[a4*4+0] + G[a4*4+0];
            const float v1 = Sreg[a4*4+1] + Ti[a4*4+1] + G[a4*4+1];
            const float v2 = Sreg[a4*4+2] + Ti[a4*4+2] + G[a4*4+2];
            const float v3 = Sreg[a4*4+3] + Ti[a4*4+3] + G[a4*4+3];
            if (v0 > bm){ bm = v0; am = a4*4+0; }
            if (v1 > bm){ bm = v1; am = a4*4+1; }
            if (v2 > bm){ bm = v2; am = a4*4+2; }
            if (v3 > bm){ bm = v3; am = a4*4+3; }
            float4 v4; v4.x=v0; v4.y=v1; v4.z=v2; v4.w=v3;
            *(float4*)(op + a4*4) = v4;
        }
        __syncthreads();

        const int ep = ev_pred_s;
        if (newev_s && tid < 34) Gt_s[tid] += Weg_s[ep-1][tid];
        if (ep > 0 && am > 0){
            const int ke = ep - 1;
            if (!((gta >> ke) & 1ull)){
                gta |= 1ull << ke;
                #pragma unroll
                for (int a=0;a<36;a++) G[a] += Wag2_s[ke][a];
            }
            const int ak = am - 1;
            if (!((garg >> ak) & 1ull)){
                garg |= 1ull << ak;
                #pragma unroll
                for (int a=0;a<36;a++) G[a] += Wag1_s[ak][a];
            }
        }
        e0a = e0a_n; e0b = e0b_n;
        __syncthreads();
    }
}

extern "C" void kernel_launch(void* const* d_in, const int* in_sizes, int n_in,
                              void* d_out, int out_size)
{
    const int*   ids  = (const int*)  d_in[0];
    const float* emb  = (const float*)d_in[1];
    const float* WihF = (const float*)d_in[2];
    const float* WhhF = (const float*)d_in[3];
    const float* bihF = (const float*)d_in[4];
    const float* bhhF = (const float*)d_in[5];
    const float* WihB = (const float*)d_in[6];
    const float* WhhB = (const float*)d_in[7];
    const float* bihB = (const float*)d_in[8];
    const float* bhhB = (const float*)d_in[9];
    const float* We   = (const float*)d_in[10];
    const float* be   = (const float*)d_in[11];
    const float* Wa   = (const float*)d_in[12];
    const float* ba   = (const float*)d_in[13];
    float* out    = (float*)d_out;
    float* evout  = out;
    float* argout = out + (long)NB*NL*NE;

    k1_zx<<<dim3(32, 32), 256>>>(ids, emb, WihF, WihB, bihF, bhhF, bihB, bhhB);
    k2_lstm<<<128, 512>>>(WhhF, WhhB);
    k3_pre<<<256, 128>>>(Wa, We, ba, be);
    k4_scan<<<16, 128>>>(Wa, We, evout, argout);
}